// round 1
// baseline (speedup 1.0000x reference)
#include <cuda_runtime.h>
#include <cstddef>

#define HS 512
#define BS 16
#define SS 2048
#define LC 32              // chunk length
#define CC 64              // number of chunks
#define MR (CC*BS)         // 1024 rows per scan step

// Scratch (static __device__ arrays; no allocation anywhere)
static __device__ float g_bxc[(size_t)SS * BS * HS];  // [i][chunk][b][h], 64MB
static __device__ float g_hs [(size_t)BS * SS * HS];  // fallback hs storage
static __device__ float g_H0[MR * HS];
static __device__ float g_H1[MR * HS];
static __device__ float g_Hi[MR * HS];                // chunk initial states
static __device__ float g_P0[HS * HS];
static __device__ float g_P1[HS * HS];

// ---------------------------------------------------------------- zero init
__global__ void k_zero()
{
    int i = blockIdx.x * blockDim.x + threadIdx.x;
    if (i < MR * HS) { g_H0[i] = 0.f; g_Hi[i] = 0.f; }
}

// ---------------------------------------------------------------- NT GEMM
// Out[r][n] = sum_k In[r][k] * W[n][k]    (both operands K-contiguous)
// 64x64 tile, BK=16, 128 threads, 4x8 micro-tile.
// mode 0: plain (In, Out as passed)   [used for ys when hs lives in d_out]
// mode 1: bx    (row-permuted In = x, Out = g_bxc)
// mode 2: ys with In = g_hs
__global__ __launch_bounds__(128) void k_gemm_nt(const float* __restrict__ In,
                                                 const float* __restrict__ W,
                                                 float* __restrict__ Out,
                                                 int mode)
{
    if (mode == 1) Out = g_bxc;
    if (mode == 2) In  = g_hs;

    __shared__ float sI[16][68];
    __shared__ float sW[16][68];

    const int tid  = threadIdx.x;
    const int row0 = blockIdx.y << 6;
    const int col0 = blockIdx.x << 6;
    const int lr   = tid >> 1;         // 0..63
    const int lk   = (tid & 1) << 3;   // 0 or 8

    int gr = row0 + lr;
    int srow = gr;
    if (mode == 1) {
        // out row r = i*1024 + j*16 + b  ->  x row = b*2048 + j*32 + i
        int i  = gr >> 10;
        int jb = gr & 1023;
        srow = (jb & 15) * SS + ((jb >> 4) << 5) + i;
    }
    const float* ip = In + (size_t)srow * HS + lk;
    const float* wp = W  + (size_t)(col0 + lr) * HS + lk;

    const int tx = tid & 7;      // col group (8 cols)
    const int ty = tid >> 3;     // row group (4 rows)

    float acc[4][8];
#pragma unroll
    for (int i = 0; i < 4; i++)
#pragma unroll
        for (int j = 0; j < 8; j++) acc[i][j] = 0.f;

    for (int k0 = 0; k0 < HS; k0 += 16) {
        float4 a0 = *(const float4*)(ip + k0);
        float4 a1 = *(const float4*)(ip + k0 + 4);
        float4 b0 = *(const float4*)(wp + k0);
        float4 b1 = *(const float4*)(wp + k0 + 4);
        sI[lk+0][lr]=a0.x; sI[lk+1][lr]=a0.y; sI[lk+2][lr]=a0.z; sI[lk+3][lr]=a0.w;
        sI[lk+4][lr]=a1.x; sI[lk+5][lr]=a1.y; sI[lk+6][lr]=a1.z; sI[lk+7][lr]=a1.w;
        sW[lk+0][lr]=b0.x; sW[lk+1][lr]=b0.y; sW[lk+2][lr]=b0.z; sW[lk+3][lr]=b0.w;
        sW[lk+4][lr]=b1.x; sW[lk+5][lr]=b1.y; sW[lk+6][lr]=b1.z; sW[lk+7][lr]=b1.w;
        __syncthreads();
#pragma unroll
        for (int k = 0; k < 16; k++) {
            float4 ri = *(const float4*)&sI[k][ty << 2];
            float4 w0 = *(const float4*)&sW[k][tx << 3];
            float4 w1 = *(const float4*)&sW[k][(tx << 3) + 4];
            float rr[4] = {ri.x, ri.y, ri.z, ri.w};
            float ww[8] = {w0.x, w0.y, w0.z, w0.w, w1.x, w1.y, w1.z, w1.w};
#pragma unroll
            for (int i = 0; i < 4; i++)
#pragma unroll
                for (int j = 0; j < 8; j++) acc[i][j] += rr[i] * ww[j];
        }
        __syncthreads();
    }
#pragma unroll
    for (int i = 0; i < 4; i++) {
        size_t o = (size_t)(row0 + (ty << 2) + i) * HS + col0 + (tx << 3);
        *(float4*)&Out[o]     = make_float4(acc[i][0], acc[i][1], acc[i][2], acc[i][3]);
        *(float4*)&Out[o + 4] = make_float4(acc[i][4], acc[i][5], acc[i][6], acc[i][7]);
    }
}

// ---------------------------------------------------------------- squaring (NN GEMM)
// P[m][n] = sum_k X[m][k] * X[k][n];  sel selects ping-pong chain A->P0->P1->...
__global__ __launch_bounds__(128) void k_sq(const float* __restrict__ A0, int sel)
{
    const float* X;
    float* Out;
    if (sel == 0)      { X = A0;   Out = g_P0; }
    else if (sel & 1)  { X = g_P0; Out = g_P1; }
    else               { X = g_P1; Out = g_P0; }

    __shared__ float sI[16][68];
    __shared__ float sW[16][68];

    const int tid  = threadIdx.x;
    const int row0 = blockIdx.y << 6;
    const int col0 = blockIdx.x << 6;
    const int lr   = tid >> 1;
    const int lk   = (tid & 1) << 3;
    const float* ip = X + (size_t)(row0 + lr) * HS + lk;
    const int kk2 = tid >> 4;            // 0..7
    const int nq  = (tid & 15) << 2;     // 0..60
    const int tx = tid & 7, ty = tid >> 3;

    float acc[4][8];
#pragma unroll
    for (int i = 0; i < 4; i++)
#pragma unroll
        for (int j = 0; j < 8; j++) acc[i][j] = 0.f;

    for (int k0 = 0; k0 < HS; k0 += 16) {
        float4 a0 = *(const float4*)(ip + k0);
        float4 a1 = *(const float4*)(ip + k0 + 4);
        float4 y0 = *(const float4*)&X[(size_t)(k0 + kk2)     * HS + col0 + nq];
        float4 y1 = *(const float4*)&X[(size_t)(k0 + kk2 + 8) * HS + col0 + nq];
        sI[lk+0][lr]=a0.x; sI[lk+1][lr]=a0.y; sI[lk+2][lr]=a0.z; sI[lk+3][lr]=a0.w;
        sI[lk+4][lr]=a1.x; sI[lk+5][lr]=a1.y; sI[lk+6][lr]=a1.z; sI[lk+7][lr]=a1.w;
        *(float4*)&sW[kk2][nq]     = y0;
        *(float4*)&sW[kk2 + 8][nq] = y1;
        __syncthreads();
#pragma unroll
        for (int k = 0; k < 16; k++) {
            float4 ri = *(const float4*)&sI[k][ty << 2];
            float4 w0 = *(const float4*)&sW[k][tx << 3];
            float4 w1 = *(const float4*)&sW[k][(tx << 3) + 4];
            float rr[4] = {ri.x, ri.y, ri.z, ri.w};
            float ww[8] = {w0.x, w0.y, w0.z, w0.w, w1.x, w1.y, w1.z, w1.w};
#pragma unroll
            for (int i = 0; i < 4; i++)
#pragma unroll
                for (int j = 0; j < 8; j++) acc[i][j] += rr[i] * ww[j];
        }
        __syncthreads();
    }
#pragma unroll
    for (int i = 0; i < 4; i++) {
        size_t o = (size_t)(row0 + (ty << 2) + i) * HS + col0 + (tx << 3);
        *(float4*)&Out[o]     = make_float4(acc[i][0], acc[i][1], acc[i][2], acc[i][3]);
        *(float4*)&Out[o + 4] = make_float4(acc[i][4], acc[i][5], acc[i][6], acc[i][7]);
    }
}

// ---------------------------------------------------------------- scan step
// Hout[r][n] = bxc[istep][r][n] + sum_k A[n][k] * Hin[r][k]
// hsmode: 0 = no hs store, 1 = store to hsp, 2 = store to g_hs
__global__ __launch_bounds__(128) void k_scan(int inbuf, int outbuf, int istep,
                                              float* __restrict__ hsp, int hsmode,
                                              const float* __restrict__ Aw)
{
    const float* Hin  = (inbuf  == 0) ? g_H0 : (inbuf  == 1) ? g_H1 : g_Hi;
    float*       Hout = (outbuf == 0) ? g_H0 : (outbuf == 1) ? g_H1 : g_Hi;
    const float* bxs  = g_bxc + (size_t)istep * MR * HS;
    if (hsmode == 2) hsp = g_hs;

    __shared__ float sI[16][68];
    __shared__ float sW[16][68];

    const int tid  = threadIdx.x;
    const int row0 = blockIdx.y << 6;
    const int col0 = blockIdx.x << 6;
    const int lr   = tid >> 1;
    const int lk   = (tid & 1) << 3;
    const float* ip = Hin + (size_t)(row0 + lr) * HS + lk;
    const float* wp = Aw  + (size_t)(col0 + lr) * HS + lk;
    const int tx = tid & 7, ty = tid >> 3;

    float acc[4][8];
#pragma unroll
    for (int i = 0; i < 4; i++)
#pragma unroll
        for (int j = 0; j < 8; j++) acc[i][j] = 0.f;

    for (int k0 = 0; k0 < HS; k0 += 16) {
        float4 a0 = *(const float4*)(ip + k0);
        float4 a1 = *(const float4*)(ip + k0 + 4);
        float4 b0 = *(const float4*)(wp + k0);
        float4 b1 = *(const float4*)(wp + k0 + 4);
        sI[lk+0][lr]=a0.x; sI[lk+1][lr]=a0.y; sI[lk+2][lr]=a0.z; sI[lk+3][lr]=a0.w;
        sI[lk+4][lr]=a1.x; sI[lk+5][lr]=a1.y; sI[lk+6][lr]=a1.z; sI[lk+7][lr]=a1.w;
        sW[lk+0][lr]=b0.x; sW[lk+1][lr]=b0.y; sW[lk+2][lr]=b0.z; sW[lk+3][lr]=b0.w;
        sW[lk+4][lr]=b1.x; sW[lk+5][lr]=b1.y; sW[lk+6][lr]=b1.z; sW[lk+7][lr]=b1.w;
        __syncthreads();
#pragma unroll
        for (int k = 0; k < 16; k++) {
            float4 ri = *(const float4*)&sI[k][ty << 2];
            float4 w0 = *(const float4*)&sW[k][tx << 3];
            float4 w1 = *(const float4*)&sW[k][(tx << 3) + 4];
            float rr[4] = {ri.x, ri.y, ri.z, ri.w};
            float ww[8] = {w0.x, w0.y, w0.z, w0.w, w1.x, w1.y, w1.z, w1.w};
#pragma unroll
            for (int i = 0; i < 4; i++)
#pragma unroll
                for (int j = 0; j < 8; j++) acc[i][j] += rr[i] * ww[j];
        }
        __syncthreads();
    }
#pragma unroll
    for (int i = 0; i < 4; i++) {
        int r = row0 + (ty << 2) + i;
        int c = col0 + (tx << 3);
        size_t o = (size_t)r * HS + c;
        float4 v0 = make_float4(acc[i][0], acc[i][1], acc[i][2], acc[i][3]);
        float4 v1 = make_float4(acc[i][4], acc[i][5], acc[i][6], acc[i][7]);
        float4 bb0 = *(const float4*)&bxs[o];
        float4 bb1 = *(const float4*)&bxs[o + 4];
        v0.x += bb0.x; v0.y += bb0.y; v0.z += bb0.z; v0.w += bb0.w;
        v1.x += bb1.x; v1.y += bb1.y; v1.z += bb1.z; v1.w += bb1.w;
        *(float4*)&Hout[o]     = v0;
        *(float4*)&Hout[o + 4] = v1;
        if (hsmode) {
            int b = r & 15, j = r >> 4;
            size_t ho = ((size_t)b * SS + (j << 5) + istep) * HS + c;
            *(float4*)&hsp[ho]     = v0;
            *(float4*)&hsp[ho + 4] = v1;
        }
    }
}

// ---------------------------------------------------------------- cross-chunk scan step
// g_Hi[j][b][n] = sum_k AL[n][k] * g_Hi[j-1][b][k] + g_H0[j-1 chunk finals][b][n]
__global__ __launch_bounds__(256) void k_cross(int j)
{
    __shared__ float sC[16][512];
    __shared__ float sA[16][68];

    const float* cprev = g_Hi + (size_t)(j - 1) * BS * HS;
    const float* fprev = g_H0 + (size_t)(j - 1) * BS * HS;
    float*       cout  = g_Hi + (size_t)j * BS * HS;
    const float* AL    = g_P0;   // A^32

    int t  = threadIdx.x;
    int n0 = blockIdx.x << 6;

    for (int e = t; e < BS * HS / 4; e += 256)
        ((float4*)&sC[0][0])[e] = ((const float4*)cprev)[e];

    int cc = t & 63, brow = t >> 6;   // brow 0..3
    int n  = n0 + cc;
    int rr = t >> 2, q = (t & 3) << 2;

    float a0 = 0.f, a1 = 0.f, a2 = 0.f, a3 = 0.f;

    for (int k0 = 0; k0 < HS; k0 += 16) {
        if (k0) __syncthreads();       // protect sA overwrite
        float4 v = *(const float4*)&AL[(size_t)(n0 + rr) * HS + k0 + q];
        sA[q + 0][rr] = v.x; sA[q + 1][rr] = v.y;
        sA[q + 2][rr] = v.z; sA[q + 3][rr] = v.w;
        __syncthreads();               // also covers the initial sC fill
#pragma unroll
        for (int kk = 0; kk < 16; kk++) {
            float a = sA[kk][cc];
            a0 += a * sC[brow     ][k0 + kk];
            a1 += a * sC[brow +  4][k0 + kk];
            a2 += a * sC[brow +  8][k0 + kk];
            a3 += a * sC[brow + 12][k0 + kk];
        }
    }
    __syncthreads();
    cout[(size_t)(brow     ) * HS + n] = a0 + fprev[(size_t)(brow     ) * HS + n];
    cout[(size_t)(brow +  4) * HS + n] = a1 + fprev[(size_t)(brow +  4) * HS + n];
    cout[(size_t)(brow +  8) * HS + n] = a2 + fprev[(size_t)(brow +  8) * HS + n];
    cout[(size_t)(brow + 12) * HS + n] = a3 + fprev[(size_t)(brow + 12) * HS + n];
}

// ---------------------------------------------------------------- launch
extern "C" void kernel_launch(void* const* d_in, const int* in_sizes, int n_in,
                              void* d_out, int out_size)
{
    const float* x  = (const float*)d_in[0];
    const float* Aw = (const float*)d_in[1];
    const float* Bw = (const float*)d_in[2];
    const float* Cw = (const float*)d_in[3];
    float* out = (float*)d_out;

    const size_t YS = (size_t)BS * SS * HS;          // 16,777,216
    bool both = (size_t)out_size >= 2 * YS;          // output = (ys, hs) concatenated
    float* hsp  = both ? out + YS : nullptr;
    int hsmode  = both ? 1 : 2;

    // 0) zero state buffers
    k_zero<<<2048, 256>>>();

    // 1) bx = x @ B^T, stored step-major: bxc[i][chunk][b][h]
    k_gemm_nt<<<dim3(8, 512), 128>>>(x, Bw, nullptr, 1);

    // 2) A^32 by repeated squaring: A->P0->P1->P0->P1->P0
    for (int s = 0; s < 5; s++)
        k_sq<<<dim3(8, 8), 128>>>(Aw, s);

    // 3) phase 1: local scans (zero init), all 64 chunks in parallel; finals land in g_H0
    for (int i = 0; i < LC; i++)
        k_scan<<<dim3(8, 16), 128>>>((i & 1) ? 1 : 0, (i & 1) ? 0 : 1, i,
                                     nullptr, 0, Aw);

    // 4) phase 2: cross-chunk scan for chunk initial states (g_Hi row 0 stays zero)
    for (int j = 1; j < CC; j++)
        k_cross<<<8, 256>>>(j);

    // 5) phase 3: local scans with correct initial states, writing hs
    for (int i = 0; i < LC; i++) {
        int inb  = (i == 0) ? 2 : ((i & 1) ? 1 : 0);
        int outb = (i & 1) ? 0 : 1;
        k_scan<<<dim3(8, 16), 128>>>(inb, outb, i, hsp, hsmode, Aw);
    }

    // 6) ys = hs @ C^T
    k_gemm_nt<<<dim3(8, 512), 128>>>(both ? out + YS : nullptr, Cw, out, both ? 0 : 2);
}

// round 3
// speedup vs baseline: 1.7724x; 1.7724x over previous
#include <cuda_runtime.h>
#include <cstddef>

#define HS 512
#define BS 16
#define SS 2048
#define LC 32              // chunk length
#define CC 64              // number of chunks
#define MR (CC*BS)         // 1024 rows per scan step

// Scratch (static __device__ arrays; no allocation anywhere)
static __device__ float g_bxc[(size_t)SS * BS * HS];  // [i][chunk][b][h]
static __device__ float g_hs [(size_t)BS * SS * HS];  // fallback hs storage
static __device__ float g_H0[MR * HS];
static __device__ float g_H1[MR * HS];
static __device__ float g_Hi[MR * HS];                // chunk initial states
static __device__ float g_P0[HS * HS];
static __device__ float g_P1[HS * HS];
static __device__ unsigned g_cntA[16];                // per-row-tile barrier counters
static __device__ unsigned g_cnt3;                    // cross-scan barrier counter

// ---------------------------------------------------------------- barrier
__device__ __forceinline__ void gbar(unsigned* cnt, unsigned target)
{
    __threadfence();
    __syncthreads();
    if (threadIdx.x == 0) {
        atomicAdd(cnt, 1u);
        while (*(volatile unsigned*)cnt < target) { __nanosleep(40); }
        __threadfence();
    }
    __syncthreads();
}

// ---------------------------------------------------------------- zero init
__global__ void k_zero()
{
    int i = blockIdx.x * blockDim.x + threadIdx.x;
    if (i < MR * HS) { g_H0[i] = 0.f; g_Hi[i] = 0.f; }
    if (i < 16) g_cntA[i] = 0u;
    if (i == 16) g_cnt3 = 0u;
}

// ---------------------------------------------------------------- big NT SGEMM
// Out[r][n] = sum_k In[r][k] * W[n][k]; 128x128 tile, BK=16, 256 thr, 8x8 micro
// mode 0: plain; mode 1: In rows permuted from x, Out = g_bxc; mode 2: In = g_hs
__global__ __launch_bounds__(256) void k_gemm_big(const float* __restrict__ In,
                                                  const float* __restrict__ W,
                                                  float* __restrict__ Out, int mode)
{
    if (mode == 1) Out = g_bxc;
    if (mode == 2) In  = g_hs;

    __shared__ float sI[2][16][132];
    __shared__ float sW[2][16][132];

    const int tid  = threadIdx.x;
    const int row0 = blockIdx.y << 7;
    const int col0 = blockIdx.x << 7;

    const int lr = tid >> 1;          // 0..127
    const int lq = (tid & 1) << 3;    // 0 or 8
    int gr = row0 + lr;
    int srow = gr;
    if (mode == 1) {
        int ii = gr >> 10;            // step i
        int jb = gr & 1023;           // chunk*16 + b
        srow = (jb & 15) * SS + ((jb >> 4) << 5) + ii;
    }
    const float* ip = In + (size_t)srow * HS + lq;
    const float* wp = W  + (size_t)(col0 + lr) * HS + lq;

    const int tx4 = (tid & 15) << 2;  // 0..60
    const int ty4 = (tid >> 4) << 2;  // 0..60

    float acc[8][8];
#pragma unroll
    for (int i = 0; i < 8; i++)
#pragma unroll
        for (int j = 0; j < 8; j++) acc[i][j] = 0.f;

    float4 ra0 = *(const float4*)(ip);
    float4 ra1 = *(const float4*)(ip + 4);
    float4 rb0 = *(const float4*)(wp);
    float4 rb1 = *(const float4*)(wp + 4);
    sI[0][lq+0][lr]=ra0.x; sI[0][lq+1][lr]=ra0.y; sI[0][lq+2][lr]=ra0.z; sI[0][lq+3][lr]=ra0.w;
    sI[0][lq+4][lr]=ra1.x; sI[0][lq+5][lr]=ra1.y; sI[0][lq+6][lr]=ra1.z; sI[0][lq+7][lr]=ra1.w;
    sW[0][lq+0][lr]=rb0.x; sW[0][lq+1][lr]=rb0.y; sW[0][lq+2][lr]=rb0.z; sW[0][lq+3][lr]=rb0.w;
    sW[0][lq+4][lr]=rb1.x; sW[0][lq+5][lr]=rb1.y; sW[0][lq+6][lr]=rb1.z; sW[0][lq+7][lr]=rb1.w;
    __syncthreads();

    for (int t = 0; t < 32; ++t) {
        const int b = t & 1;
        if (t < 31) {
            const int ko = (t + 1) << 4;
            ra0 = *(const float4*)(ip + ko);
            ra1 = *(const float4*)(ip + ko + 4);
            rb0 = *(const float4*)(wp + ko);
            rb1 = *(const float4*)(wp + ko + 4);
        }
#pragma unroll
        for (int k = 0; k < 16; ++k) {
            float4 i0 = *(const float4*)&sI[b][k][ty4];
            float4 i1 = *(const float4*)&sI[b][k][64 + ty4];
            float4 w0 = *(const float4*)&sW[b][k][tx4];
            float4 w1 = *(const float4*)&sW[b][k][64 + tx4];
            float rr_[8] = {i0.x,i0.y,i0.z,i0.w,i1.x,i1.y,i1.z,i1.w};
            float ww_[8] = {w0.x,w0.y,w0.z,w0.w,w1.x,w1.y,w1.z,w1.w};
#pragma unroll
            for (int i = 0; i < 8; i++)
#pragma unroll
                for (int j = 0; j < 8; j++)
                    acc[i][j] += rr_[i] * ww_[j];
        }
        if (t < 31) {
            const int nb = b ^ 1;
            sI[nb][lq+0][lr]=ra0.x; sI[nb][lq+1][lr]=ra0.y; sI[nb][lq+2][lr]=ra0.z; sI[nb][lq+3][lr]=ra0.w;
            sI[nb][lq+4][lr]=ra1.x; sI[nb][lq+5][lr]=ra1.y; sI[nb][lq+6][lr]=ra1.z; sI[nb][lq+7][lr]=ra1.w;
            sW[nb][lq+0][lr]=rb0.x; sW[nb][lq+1][lr]=rb0.y; sW[nb][lq+2][lr]=rb0.z; sW[nb][lq+3][lr]=rb0.w;
            sW[nb][lq+4][lr]=rb1.x; sW[nb][lq+5][lr]=rb1.y; sW[nb][lq+6][lr]=rb1.z; sW[nb][lq+7][lr]=rb1.w;
            __syncthreads();
        }
    }

#pragma unroll
    for (int i = 0; i < 8; i++) {
        int r = row0 + ((i < 4) ? (ty4 + i) : (64 + ty4 + i - 4));
        size_t o = (size_t)r * HS + col0;
        *(float4*)&Out[o + tx4]      = make_float4(acc[i][0], acc[i][1], acc[i][2], acc[i][3]);
        *(float4*)&Out[o + 64 + tx4] = make_float4(acc[i][4], acc[i][5], acc[i][6], acc[i][7]);
    }
}

// ---------------------------------------------------------------- squaring (NN GEMM)
// P[m][n] = sum_k X[m][k] * X[k][n];  sel: A->P0->P1->P0->P1->P0
__global__ __launch_bounds__(128) void k_sq(const float* __restrict__ A0, int sel)
{
    const float* X;
    float* Out;
    if (sel == 0)      { X = A0;   Out = g_P0; }
    else if (sel & 1)  { X = g_P0; Out = g_P1; }
    else               { X = g_P1; Out = g_P0; }

    __shared__ float sI[16][68];
    __shared__ float sW[16][68];

    const int tid  = threadIdx.x;
    const int row0 = blockIdx.y << 6;
    const int col0 = blockIdx.x << 6;
    const int lr   = tid >> 1;
    const int lk   = (tid & 1) << 3;
    const float* ip = X + (size_t)(row0 + lr) * HS + lk;
    const int kk2 = tid >> 4;            // 0..7
    const int nq  = (tid & 15) << 2;     // 0..60
    const int tx = tid & 7, ty = tid >> 3;

    float acc[4][8];
#pragma unroll
    for (int i = 0; i < 4; i++)
#pragma unroll
        for (int j = 0; j < 8; j++) acc[i][j] = 0.f;

    for (int k0 = 0; k0 < HS; k0 += 16) {
        float4 a0 = *(const float4*)(ip + k0);
        float4 a1 = *(const float4*)(ip + k0 + 4);
        float4 y0 = *(const float4*)&X[(size_t)(k0 + kk2)     * HS + col0 + nq];
        float4 y1 = *(const float4*)&X[(size_t)(k0 + kk2 + 8) * HS + col0 + nq];
        sI[lk+0][lr]=a0.x; sI[lk+1][lr]=a0.y; sI[lk+2][lr]=a0.z; sI[lk+3][lr]=a0.w;
        sI[lk+4][lr]=a1.x; sI[lk+5][lr]=a1.y; sI[lk+6][lr]=a1.z; sI[lk+7][lr]=a1.w;
        *(float4*)&sW[kk2][nq]     = y0;
        *(float4*)&sW[kk2 + 8][nq] = y1;
        __syncthreads();
#pragma unroll
        for (int k = 0; k < 16; k++) {
            float4 ri = *(const float4*)&sI[k][ty << 2];
            float4 w0 = *(const float4*)&sW[k][tx << 3];
            float4 w1 = *(const float4*)&sW[k][(tx << 3) + 4];
            float rr[4] = {ri.x, ri.y, ri.z, ri.w};
            float ww[8] = {w0.x, w0.y, w0.z, w0.w, w1.x, w1.y, w1.z, w1.w};
#pragma unroll
            for (int i = 0; i < 4; i++)
#pragma unroll
                for (int j = 0; j < 8; j++) acc[i][j] += rr[i] * ww[j];
        }
        __syncthreads();
    }
#pragma unroll
    for (int i = 0; i < 4; i++) {
        size_t o = (size_t)(row0 + (ty << 2) + i) * HS + col0 + (tx << 3);
        *(float4*)&Out[o]     = make_float4(acc[i][0], acc[i][1], acc[i][2], acc[i][3]);
        *(float4*)&Out[o + 4] = make_float4(acc[i][4], acc[i][5], acc[i][6], acc[i][7]);
    }
}

// ---------------------------------------------------------------- persistent scan
// One launch runs all LC steps. Grid (8 col-tiles, 16 row-tiles), 256 threads.
// A columns for this block's col-tile stay resident in smem for all steps.
// Cross-step sync only among the 8 blocks of the same row tile.
#define SCAN_SMEM ((512*68 + 2*16*68) * 4)

__global__ __launch_bounds__(256) void k_scan_persist(int phase, float* __restrict__ hsp,
                                                      int hsmode, const float* __restrict__ Aw)
{
    extern __shared__ float sm[];
    float* sA = sm;                 // [512][68]  (k-major, 64 A-rows of this col tile)
    float* sH = sm + 512 * 68;      // [2][16][68] double-buffered H chunk

    const int tid  = threadIdx.x;
    const int col0 = blockIdx.x << 6;
    const int rb   = blockIdx.y;
    const int row0 = rb << 6;

    if (hsmode == 2) hsp = g_hs;

    // one-time preload of A[col0..col0+63][*] transposed into sA[k][n]
    for (int e = tid; e < 64 * 128; e += 256) {
        int rr = e >> 7;              // 0..63 (A row within tile)
        int kq = (e & 127) << 2;      // k offset
        float4 v = *(const float4*)&Aw[(size_t)(col0 + rr) * HS + kq];
        sA[(kq+0)*68 + rr] = v.x;
        sA[(kq+1)*68 + rr] = v.y;
        sA[(kq+2)*68 + rr] = v.z;
        sA[(kq+3)*68 + rr] = v.w;
    }
    __syncthreads();

    const int tx4 = (tid & 15) << 2;  // out col offset
    const int ty4 = (tid >> 4) << 2;  // out row offset
    const int lr  = tid >> 2;         // loader row 0..63
    const int lq  = (tid & 3) << 2;   // loader k offset 0..12
    const unsigned base = phase ? (8u * LC) : 0u;
    unsigned* cnt = &g_cntA[rb];

    for (int i = 0; i < LC; ++i) {
        const float* Hin;
        if (i == 0) Hin = phase ? g_Hi : g_H0;
        else        Hin = (i & 1) ? g_H1 : g_H0;
        float* Hout = (i & 1) ? g_H0 : g_H1;
        const float* bxs = g_bxc + (size_t)i * MR * HS;

        float acc[4][4];
#pragma unroll
        for (int a = 0; a < 4; a++)
#pragma unroll
            for (int c = 0; c < 4; c++) acc[a][c] = 0.f;

        const float* hrow = Hin + (size_t)(row0 + lr) * HS + lq;

        float4 h0 = *(const float4*)hrow;
        sH[(lq+0)*68 + lr] = h0.x;
        sH[(lq+1)*68 + lr] = h0.y;
        sH[(lq+2)*68 + lr] = h0.z;
        sH[(lq+3)*68 + lr] = h0.w;
        __syncthreads();

        for (int t = 0; t < 32; ++t) {
            const int b = t & 1;
            float4 nh;
            if (t < 31) nh = *(const float4*)(hrow + ((t + 1) << 4));
            const float* sAk = sA + (t << 4) * 68;
            const float* sHk = sH + (b << 4) * 68;
#pragma unroll
            for (int k = 0; k < 16; ++k) {
                float4 hv = *(const float4*)&sHk[k*68 + ty4];
                float4 av = *(const float4*)&sAk[k*68 + tx4];
                float hh[4] = {hv.x, hv.y, hv.z, hv.w};
                float aa[4] = {av.x, av.y, av.z, av.w};
#pragma unroll
                for (int a = 0; a < 4; a++)
#pragma unroll
                    for (int c = 0; c < 4; c++)
                        acc[a][c] += hh[a] * aa[c];
            }
            if (t < 31) {
                float* d = sH + ((b ^ 1) << 4) * 68;
                d[(lq+0)*68 + lr] = nh.x;
                d[(lq+1)*68 + lr] = nh.y;
                d[(lq+2)*68 + lr] = nh.z;
                d[(lq+3)*68 + lr] = nh.w;
                __syncthreads();
            }
        }

        // epilogue: add bx, write Hout (+ optional hs)
#pragma unroll
        for (int a = 0; a < 4; a++) {
            int r = row0 + ty4 + a;
            size_t o = (size_t)r * HS + col0 + tx4;
            float4 bb = *(const float4*)&bxs[o];
            float4 v = make_float4(acc[a][0] + bb.x, acc[a][1] + bb.y,
                                   acc[a][2] + bb.z, acc[a][3] + bb.w);
            *(float4*)&Hout[o] = v;
            if (hsmode) {
                int bidx = r & 15, jj = r >> 4;
                size_t ho = ((size_t)bidx * SS + (jj << 5) + i) * HS + col0 + tx4;
                *(float4*)&hsp[ho] = v;
            }
        }
        gbar(cnt, base + 8u * (i + 1));
    }
}

// ---------------------------------------------------------------- persistent cross scan
// g_Hi[j] = A^32 * g_Hi[j-1] + finals[j-1];  63 steps in one launch, 32 blocks.
__global__ __launch_bounds__(256) void k_cross_persist()
{
    __shared__ float sS[16][516];
    const float* AL = g_P0;              // A^32
    const int t  = threadIdx.x;
    const int n0 = blockIdx.x << 4;      // 32 blocks x 16 cols
    const int r  = t & 15;
    const int no = t >> 4;
    const int n  = n0 + no;
    const float* arow = AL + (size_t)n * HS;

    for (int j = 1; j < CC; ++j) {
        const float* sprev = g_Hi + (size_t)(j - 1) * BS * HS;
        const float* fprev = g_H0 + (size_t)(j - 1) * BS * HS;
        float*       sout  = g_Hi + (size_t)j * BS * HS;

        for (int e = t; e < BS * HS / 4; e += 256) {
            float4 v = ((const float4*)sprev)[e];
            int rr = e >> 7;
            int kk = (e & 127) << 2;
            *(float4*)&sS[rr][kk] = v;
        }
        __syncthreads();

        float a0 = 0.f, a1 = 0.f, a2 = 0.f, a3 = 0.f;
#pragma unroll 4
        for (int k = 0; k < HS; k += 16) {
            float4 v0 = *(const float4*)&arow[k];
            float4 v1 = *(const float4*)&arow[k + 4];
            float4 v2 = *(const float4*)&arow[k + 8];
            float4 v3 = *(const float4*)&arow[k + 12];
            a0 += v0.x*sS[r][k+0]  + v0.y*sS[r][k+1]  + v0.z*sS[r][k+2]  + v0.w*sS[r][k+3];
            a1 += v1.x*sS[r][k+4]  + v1.y*sS[r][k+5]  + v1.z*sS[r][k+6]  + v1.w*sS[r][k+7];
            a2 += v2.x*sS[r][k+8]  + v2.y*sS[r][k+9]  + v2.z*sS[r][k+10] + v2.w*sS[r][k+11];
            a3 += v3.x*sS[r][k+12] + v3.y*sS[r][k+13] + v3.z*sS[r][k+14] + v3.w*sS[r][k+15];
        }
        sout[(size_t)r * HS + n] = (a0 + a1) + (a2 + a3) + fprev[(size_t)r * HS + n];
        gbar(&g_cnt3, 32u * (unsigned)j);
    }
}

// ---------------------------------------------------------------- launch
extern "C" void kernel_launch(void* const* d_in, const int* in_sizes, int n_in,
                              void* d_out, int out_size)
{
    const float* x  = (const float*)d_in[0];
    const float* Aw = (const float*)d_in[1];
    const float* Bw = (const float*)d_in[2];
    const float* Cw = (const float*)d_in[3];
    float* out = (float*)d_out;

    const size_t YS = (size_t)BS * SS * HS;
    bool both = (size_t)out_size >= 2 * YS;     // output = (ys, hs) concatenated
    float* hsp = both ? out + YS : nullptr;
    int hsmode = both ? 1 : 2;

    cudaFuncSetAttribute(k_scan_persist,
                         cudaFuncAttributeMaxDynamicSharedMemorySize, SCAN_SMEM);

    // 0) zero states + barrier counters
    k_zero<<<2048, 256>>>();

    // 1) bx = x @ B^T, step-major layout
    k_gemm_big<<<dim3(4, 256), 256>>>(x, Bw, nullptr, 1);

    // 2) A^32 by repeated squaring
    for (int s = 0; s < 5; s++)
        k_sq<<<dim3(8, 8), 128>>>(Aw, s);

    // 3) phase 1: local scans (zero init), persistent
    k_scan_persist<<<dim3(8, 16), 256, SCAN_SMEM>>>(0, nullptr, 0, Aw);

    // 4) phase 2: cross-chunk scan, persistent
    k_cross_persist<<<32, 256>>>();

    // 5) phase 3: local scans with true initial states, writes hs
    k_scan_persist<<<dim3(8, 16), 256, SCAN_SMEM>>>(1, hsp, hsmode, Aw);

    // 6) ys = hs @ C^T
    k_gemm_big<<<dim3(4, 256), 256>>>(both ? out + YS : nullptr, Cw, out, both ? 0 : 2);
}

// round 6
// speedup vs baseline: 1.9641x; 1.1082x over previous
#include <cuda_runtime.h>
#include <cuda_bf16.h>
#include <cstdint>
#include <cstddef>

#define HS 512
#define BS 16
#define SS 2048
#define LC 32              // chunk length
#define CC 64              // number of chunks
#define MR (CC*BS)         // 1024 rows per scan step
#define GM 32768           // big-GEMM M (BS*SS)

// ---------------- scratch (static __device__; no allocation anywhere) ----------------
static __device__ float g_bxc[(size_t)SS * BS * HS];   // [i][chunk][b][h]
static __device__ float g_hs [(size_t)BS * SS * HS];   // fallback hs storage
static __device__ float g_H0[MR * HS];
static __device__ float g_H1[MR * HS];
static __device__ float g_Hi[MR * HS];                 // chunk initial states
static __device__ float g_P0[HS * HS];
static __device__ float g_P1[HS * HS];
static __device__ __nv_bfloat16 g_Ahi[(size_t)GM * HS];  // GEMM A operand hi
static __device__ __nv_bfloat16 g_Alo[(size_t)GM * HS];  // GEMM A operand lo
static __device__ __nv_bfloat16 g_Whi[HS * HS];
static __device__ __nv_bfloat16 g_Wlo[HS * HS];
static __device__ unsigned g_cntA[16];                 // per-row-tile scan barrier
static __device__ unsigned g_cnt3;                     // cross-scan barrier
static __device__ unsigned g_cntS;                     // fused-squaring barrier

// ---------------- warp MMA helpers (sm_80-era, valid on sm_100 base) ----------------
__device__ __forceinline__ uint32_t smem_u32(const void* p) {
    uint32_t a;
    asm("{ .reg .u64 t; cvta.to.shared.u64 t, %1; cvt.u32.u64 %0, t; }" : "=r"(a) : "l"(p));
    return a;
}
__device__ __forceinline__ void ldmx4(uint32_t* r, uint32_t addr)
{
    asm volatile("ldmatrix.sync.aligned.m8n8.x4.shared.b16 {%0,%1,%2,%3}, [%4];"
        : "=r"(r[0]), "=r"(r[1]), "=r"(r[2]), "=r"(r[3]) : "r"(addr));
}
__device__ __forceinline__ void mma16816(float* c, const uint32_t* a, const uint32_t* b)
{
    asm volatile(
        "mma.sync.aligned.m16n8k16.row.col.f32.bf16.bf16.f32 "
        "{%0,%1,%2,%3}, {%4,%5,%6,%7}, {%8,%9}, {%0,%1,%2,%3};"
        : "+f"(c[0]), "+f"(c[1]), "+f"(c[2]), "+f"(c[3])
        : "r"(a[0]), "r"(a[1]), "r"(a[2]), "r"(a[3]), "r"(b[0]), "r"(b[1]));
}

// ---------------- fp32 -> bf16 hi/lo split of 4 packed floats ----------------
__device__ __forceinline__ void split4(float4 v, uint2& h, uint2& l)
{
    __nv_bfloat162 h01 = __floats2bfloat162_rn(v.x, v.y);
    __nv_bfloat162 h23 = __floats2bfloat162_rn(v.z, v.w);
    float2 f01 = __bfloat1622float2(h01);
    float2 f23 = __bfloat1622float2(h23);
    __nv_bfloat162 l01 = __floats2bfloat162_rn(v.x - f01.x, v.y - f01.y);
    __nv_bfloat162 l23 = __floats2bfloat162_rn(v.z - f23.x, v.w - f23.y);
    h.x = *reinterpret_cast<uint32_t*>(&h01);
    h.y = *reinterpret_cast<uint32_t*>(&h23);
    l.x = *reinterpret_cast<uint32_t*>(&l01);
    l.y = *reinterpret_cast<uint32_t*>(&l23);
}

// ---------------- global barrier (co-resident grids only) ----------------
__device__ __forceinline__ void gbar(unsigned* cnt, unsigned target)
{
    __threadfence();
    __syncthreads();
    if (threadIdx.x == 0) {
        atomicAdd(cnt, 1u);
        while (*(volatile unsigned*)cnt < target) { __nanosleep(40); }
        __threadfence();
    }
    __syncthreads();
}

// ---------------- zero init ----------------
__global__ void k_zero()
{
    int i = blockIdx.x * blockDim.x + threadIdx.x;
    if (i < MR * HS) { g_H0[i] = 0.f; g_Hi[i] = 0.f; }
    if (i < 16) g_cntA[i] = 0u;
    if (i == 16) g_cnt3 = 0u;
    if (i == 17) g_cntS = 0u;
}

// ---------------- split kernels ----------------
// x (permuted rows for step-major bx) -> g_Ahi/g_Alo.  One block per GEMM row.
__global__ __launch_bounds__(128) void k_split_x(const float* __restrict__ x)
{
    int r  = blockIdx.x;                   // gemm row
    int ii = r >> 10;
    int jb = r & 1023;
    int srow = (jb & 15) * SS + ((jb >> 4) << 5) + ii;
    int c = threadIdx.x << 2;
    float4 v = *(const float4*)&x[(size_t)srow * HS + c];
    uint2 h, l;
    split4(v, h, l);
    *(uint2*)((char*)g_Ahi + ((size_t)r * HS + c) * 2) = h;
    *(uint2*)((char*)g_Alo + ((size_t)r * HS + c) * 2) = l;
}

// weight (512x512) -> g_Whi/g_Wlo
__global__ __launch_bounds__(128) void k_split_w(const float* __restrict__ W)
{
    int r = blockIdx.x;
    int c = threadIdx.x << 2;
    float4 v = *(const float4*)&W[(size_t)r * HS + c];
    uint2 h, l;
    split4(v, h, l);
    *(uint2*)((char*)g_Whi + ((size_t)r * HS + c) * 2) = h;
    *(uint2*)((char*)g_Wlo + ((size_t)r * HS + c) * 2) = l;
}

// ---------------- bf16x3 GEMM via mma.sync ----------------
// Out[r][n] = sum_k (Ahi+Alo)[r][k] * (Whi+Wlo)[n][k], M=32768, N=512, K=512
// 128x128 CTA tile, 8 warps (2 m x 4 n), warp tile 64x32, K chunk 64.
// smem rows stride 72 halves (144B) -> conflict-free ldmatrix.
#define GEMM_SMEM (4 * 128 * 72 * 2)     // 73728 bytes

__global__ __launch_bounds__(256) void k_gemm_mma(float* __restrict__ Out, int mode)
{
    if (mode == 1) Out = g_bxc;
    extern __shared__ __nv_bfloat16 sb[];
    __nv_bfloat16* sAh = sb;
    __nv_bfloat16* sAl = sb + 9216;      // 128*72
    __nv_bfloat16* sWh = sb + 18432;
    __nv_bfloat16* sWl = sb + 27648;

    const int tid  = threadIdx.x;
    const int lane = tid & 31;
    const int wid  = tid >> 5;
    const int row0 = blockIdx.y << 7;
    const int col0 = blockIdx.x << 7;
    const int wm   = wid >> 2;          // 0..1
    const int wn   = wid & 3;           // 0..3

    const int lrow = tid >> 1;          // 0..127
    const int lseg = (tid & 1) << 5;    // 0 or 32 halves

    float acc[4][4][4];
#pragma unroll
    for (int mt = 0; mt < 4; ++mt)
#pragma unroll
        for (int nt = 0; nt < 4; ++nt)
#pragma unroll
            for (int q = 0; q < 4; ++q) acc[mt][nt][q] = 0.f;

    const uint32_t sAh32 = smem_u32(sAh);
    const uint32_t sAl32 = smem_u32(sAl);
    const uint32_t sWh32 = smem_u32(sWh);
    const uint32_t sWl32 = smem_u32(sWl);

    // ldmatrix lane addressing: row = lane%16, k-half = (lane>>4)*8
    const uint32_t a_lrow = (uint32_t)(wm * 64 + (lane & 15));
    const uint32_t b_lrow = (uint32_t)(wn * 32 + (lane & 15));
    const uint32_t khalf  = (uint32_t)((lane >> 4) << 3);

    for (int kc = 0; kc < 8; ++kc) {
        __syncthreads();
        {
            const size_t gA = (size_t)(row0 + lrow) * HS + kc * 64 + lseg;
            const size_t gW = (size_t)(col0 + lrow) * HS + kc * 64 + lseg;
            const uint32_t so = (uint32_t)(lrow * 72 + lseg);
#pragma unroll
            for (int i = 0; i < 4; ++i) {
                *(uint4*)(sAh + so + i*8) = *(const uint4*)(g_Ahi + gA + i*8);
                *(uint4*)(sAl + so + i*8) = *(const uint4*)(g_Alo + gA + i*8);
                *(uint4*)(sWh + so + i*8) = *(const uint4*)(g_Whi + gW + i*8);
                *(uint4*)(sWl + so + i*8) = *(const uint4*)(g_Wlo + gW + i*8);
            }
        }
        __syncthreads();

#pragma unroll
        for (int ks = 0; ks < 4; ++ks) {
            const uint32_t kcol = (uint32_t)(ks * 16) + khalf;
            uint32_t ah[4][4], al[4][4], bh[4][2], bl[4][2];
#pragma unroll
            for (int mt = 0; mt < 4; ++mt) {
                uint32_t off = ((a_lrow + mt*16) * 72 + kcol) * 2;
                ldmx4(ah[mt], sAh32 + off);
                ldmx4(al[mt], sAl32 + off);
            }
#pragma unroll
            for (int bt = 0; bt < 2; ++bt) {
                uint32_t off = ((b_lrow + bt*16) * 72 + kcol) * 2;
                uint32_t qh[4], ql[4];
                ldmx4(qh, sWh32 + off);
                ldmx4(ql, sWl32 + off);
                // tiles: r0 = n0-7/k0-7, r1 = n8-15/k0-7, r2 = n0-7/k8-15, r3 = n8-15/k8-15
                bh[2*bt+0][0] = qh[0]; bh[2*bt+0][1] = qh[2];
                bh[2*bt+1][0] = qh[1]; bh[2*bt+1][1] = qh[3];
                bl[2*bt+0][0] = ql[0]; bl[2*bt+0][1] = ql[2];
                bl[2*bt+1][0] = ql[1]; bl[2*bt+1][1] = ql[3];
            }
#pragma unroll
            for (int mt = 0; mt < 4; ++mt)
#pragma unroll
                for (int nt = 0; nt < 4; ++nt) {
                    mma16816(acc[mt][nt], ah[mt], bh[nt]);
                    mma16816(acc[mt][nt], ah[mt], bl[nt]);
                    mma16816(acc[mt][nt], al[mt], bh[nt]);
                }
        }
    }

    // epilogue: direct stores (thread t owns rows t/4, t/4+8; cols 2*(t%4)+{0,1})
    const int r_base = row0 + wm * 64 + (lane >> 2);
    const int c_base = col0 + wn * 32 + ((lane & 3) << 1);
#pragma unroll
    for (int mt = 0; mt < 4; ++mt)
#pragma unroll
        for (int nt = 0; nt < 4; ++nt) {
            size_t o0 = (size_t)(r_base + mt*16)     * HS + c_base + nt*8;
            size_t o1 = (size_t)(r_base + mt*16 + 8) * HS + c_base + nt*8;
            *(float2*)&Out[o0] = make_float2(acc[mt][nt][0], acc[mt][nt][1]);
            *(float2*)&Out[o1] = make_float2(acc[mt][nt][2], acc[mt][nt][3]);
        }
}

// ---------------- fused squarings: A^32 via 5 squarings, one launch ----------------
__global__ __launch_bounds__(128) void k_sq_fused(const float* __restrict__ A0)
{
    __shared__ float sI[16][68];
    __shared__ float sW[16][68];

    const int tid  = threadIdx.x;
    const int row0 = (blockIdx.x >> 3) << 6;
    const int col0 = (blockIdx.x & 7) << 6;
    const int lr   = tid >> 1;
    const int lk   = (tid & 1) << 3;
    const int kk2  = tid >> 4;
    const int nq   = (tid & 15) << 2;
    const int tx = tid & 7, ty = tid >> 3;

    for (int s = 0; s < 5; ++s) {
        const float* X;
        float* Outp;
        if (s == 0)      { X = A0;   Outp = g_P0; }
        else if (s & 1)  { X = g_P0; Outp = g_P1; }
        else             { X = g_P1; Outp = g_P0; }

        const float* ip = X + (size_t)(row0 + lr) * HS + lk;

        float acc[4][8];
#pragma unroll
        for (int i = 0; i < 4; i++)
#pragma unroll
            for (int j = 0; j < 8; j++) acc[i][j] = 0.f;

        for (int k0 = 0; k0 < HS; k0 += 16) {
            float4 a0 = *(const float4*)(ip + k0);
            float4 a1 = *(const float4*)(ip + k0 + 4);
            float4 y0 = *(const float4*)&X[(size_t)(k0 + kk2)     * HS + col0 + nq];
            float4 y1 = *(const float4*)&X[(size_t)(k0 + kk2 + 8) * HS + col0 + nq];
            sI[lk+0][lr]=a0.x; sI[lk+1][lr]=a0.y; sI[lk+2][lr]=a0.z; sI[lk+3][lr]=a0.w;
            sI[lk+4][lr]=a1.x; sI[lk+5][lr]=a1.y; sI[lk+6][lr]=a1.z; sI[lk+7][lr]=a1.w;
            *(float4*)&sW[kk2][nq]     = y0;
            *(float4*)&sW[kk2 + 8][nq] = y1;
            __syncthreads();
#pragma unroll
            for (int k = 0; k < 16; k++) {
                float4 ri = *(const float4*)&sI[k][ty << 2];
                float4 w0 = *(const float4*)&sW[k][tx << 3];
                float4 w1 = *(const float4*)&sW[k][(tx << 3) + 4];
                float rr[4] = {ri.x, ri.y, ri.z, ri.w};
                float ww[8] = {w0.x, w0.y, w0.z, w0.w, w1.x, w1.y, w1.z, w1.w};
#pragma unroll
                for (int i = 0; i < 4; i++)
#pragma unroll
                    for (int j = 0; j < 8; j++) acc[i][j] += rr[i] * ww[j];
            }
            __syncthreads();
        }
#pragma unroll
        for (int i = 0; i < 4; i++) {
            size_t o = (size_t)(row0 + (ty << 2) + i) * HS + col0 + (tx << 3);
            *(float4*)&Outp[o]     = make_float4(acc[i][0], acc[i][1], acc[i][2], acc[i][3]);
            *(float4*)&Outp[o + 4] = make_float4(acc[i][4], acc[i][5], acc[i][6], acc[i][7]);
        }
        gbar(&g_cntS, 64u * (unsigned)(s + 1));
    }
}

// ---------------- persistent local scan ----------------
#define SCAN_SMEM ((512*68 + 2*16*68) * 4)

__global__ __launch_bounds__(256) void k_scan_persist(int phase, float* __restrict__ hsp,
                                                      int hsmode, const float* __restrict__ Aw)
{
    extern __shared__ float sm[];
    float* sA = sm;                 // [512][68]
    float* sH = sm + 512 * 68;      // [2][16][68]

    const int tid  = threadIdx.x;
    const int col0 = blockIdx.x << 6;
    const int rb   = blockIdx.y;
    const int row0 = rb << 6;

    if (hsmode == 2) hsp = g_hs;

    for (int e = tid; e < 64 * 128; e += 256) {
        int rr = e >> 7;
        int kq = (e & 127) << 2;
        float4 v = *(const float4*)&Aw[(size_t)(col0 + rr) * HS + kq];
        sA[(kq+0)*68 + rr] = v.x;
        sA[(kq+1)*68 + rr] = v.y;
        sA[(kq+2)*68 + rr] = v.z;
        sA[(kq+3)*68 + rr] = v.w;
    }
    __syncthreads();

    const int tx4 = (tid & 15) << 2;
    const int ty4 = (tid >> 4) << 2;
    const int lr  = tid >> 2;
    const int lq  = (tid & 3) << 2;
    const unsigned base = phase ? (8u * LC) : 0u;
    unsigned* cnt = &g_cntA[rb];

    for (int i = 0; i < LC; ++i) {
        const float* Hin;
        if (i == 0) Hin = phase ? g_Hi : g_H0;
        else        Hin = (i & 1) ? g_H1 : g_H0;
        float* Hout = (i & 1) ? g_H0 : g_H1;
        const float* bxs = g_bxc + (size_t)i * MR * HS;

        float acc[4][4];
#pragma unroll
        for (int a = 0; a < 4; a++)
#pragma unroll
            for (int c = 0; c < 4; c++) acc[a][c] = 0.f;

        const float* hrow = Hin + (size_t)(row0 + lr) * HS + lq;

        float4 h0 = *(const float4*)hrow;
        sH[(lq+0)*68 + lr] = h0.x;
        sH[(lq+1)*68 + lr] = h0.y;
        sH[(lq+2)*68 + lr] = h0.z;
        sH[(lq+3)*68 + lr] = h0.w;
        __syncthreads();

        for (int t = 0; t < 32; ++t) {
            const int b = t & 1;
            float4 nh;
            if (t < 31) nh = *(const float4*)(hrow + ((t + 1) << 4));
            const float* sAk = sA + (t << 4) * 68;
            const float* sHk = sH + (b << 4) * 68;
#pragma unroll
            for (int k = 0; k < 16; ++k) {
                float4 hv = *(const float4*)&sHk[k*68 + ty4];
                float4 av = *(const float4*)&sAk[k*68 + tx4];
                float hh[4] = {hv.x, hv.y, hv.z, hv.w};
                float aa[4] = {av.x, av.y, av.z, av.w};
#pragma unroll
                for (int a = 0; a < 4; a++)
#pragma unroll
                    for (int c = 0; c < 4; c++)
                        acc[a][c] += hh[a] * aa[c];
            }
            if (t < 31) {
                float* d = sH + ((b ^ 1) << 4) * 68;
                d[(lq+0)*68 + lr] = nh.x;
                d[(lq+1)*68 + lr] = nh.y;
                d[(lq+2)*68 + lr] = nh.z;
                d[(lq+3)*68 + lr] = nh.w;
                __syncthreads();
            }
        }

#pragma unroll
        for (int a = 0; a < 4; a++) {
            int r = row0 + ty4 + a;
            size_t o = (size_t)r * HS + col0 + tx4;
            float4 bb = *(const float4*)&bxs[o];
            float4 v = make_float4(acc[a][0] + bb.x, acc[a][1] + bb.y,
                                   acc[a][2] + bb.z, acc[a][3] + bb.w);
            *(float4*)&Hout[o] = v;
            if (hsmode) {
                int bidx = r & 15, jj = r >> 4;
                size_t hrow_idx = (size_t)bidx * SS + (jj << 5) + i;
                size_t ho = hrow_idx * HS + col0 + tx4;
                *(float4*)&hsp[ho] = v;
                // fold bf16 hi/lo split for the ys GEMM
                uint2 hh, ll;
                split4(v, hh, ll);
                *(uint2*)((char*)g_Ahi + ho * 2) = hh;
                *(uint2*)((char*)g_Alo + ho * 2) = ll;
            }
        }
        gbar(cnt, base + 8u * (i + 1));
    }
}

// ---------------- persistent cross-chunk scan ----------------
__global__ __launch_bounds__(256) void k_cross_persist()
{
    __shared__ float sS[16][516];
    const float* AL = g_P0;              // A^32
    const int t  = threadIdx.x;
    const int n0 = blockIdx.x << 4;
    const int r  = t & 15;
    const int no = t >> 4;
    const int n  = n0 + no;
    const float* arow = AL + (size_t)n * HS;

    for (int j = 1; j < CC; ++j) {
        const float* sprev = g_Hi + (size_t)(j - 1) * BS * HS;
        const float* fprev = g_H0 + (size_t)(j - 1) * BS * HS;
        float*       sout  = g_Hi + (size_t)j * BS * HS;

        for (int e = t; e < BS * HS / 4; e += 256) {
            float4 v = ((const float4*)sprev)[e];
            int rr = e >> 7;
            int kk = (e & 127) << 2;
            *(float4*)&sS[rr][kk] = v;
        }
        __syncthreads();

        float a0 = 0.f, a1 = 0.f, a2 = 0.f, a3 = 0.f;
#pragma unroll 4
        for (int k = 0; k < HS; k += 16) {
            float4 v0 = *(const float4*)&arow[k];
            float4 v1 = *(const float4*)&arow[k + 4];
            float4 v2 = *(const float4*)&arow[k + 8];
            float4 v3 = *(const float4*)&arow[k + 12];
            a0 += v0.x*sS[r][k+0]  + v0.y*sS[r][k+1]  + v0.z*sS[r][k+2]  + v0.w*sS[r][k+3];
            a1 += v1.x*sS[r][k+4]  + v1.y*sS[r][k+5]  + v1.z*sS[r][k+6]  + v1.w*sS[r][k+7];
            a2 += v2.x*sS[r][k+8]  + v2.y*sS[r][k+9]  + v2.z*sS[r][k+10] + v2.w*sS[r][k+11];
            a3 += v3.x*sS[r][k+12] + v3.y*sS[r][k+13] + v3.z*sS[r][k+14] + v3.w*sS[r][k+15];
        }
        sout[(size_t)r * HS + n] = (a0 + a1) + (a2 + a3) + fprev[(size_t)r * HS + n];
        gbar(&g_cnt3, 32u * (unsigned)j);
    }
}

// ---------------- launch ----------------
extern "C" void kernel_launch(void* const* d_in, const int* in_sizes, int n_in,
                              void* d_out, int out_size)
{
    const float* x  = (const float*)d_in[0];
    const float* Aw = (const float*)d_in[1];
    const float* Bw = (const float*)d_in[2];
    const float* Cw = (const float*)d_in[3];
    float* out = (float*)d_out;

    const size_t YS = (size_t)BS * SS * HS;
    bool both = (size_t)out_size >= 2 * YS;     // output = (ys, hs) concatenated
    float* hsp = both ? out + YS : nullptr;
    int hsmode = both ? 1 : 2;

    cudaFuncSetAttribute(k_scan_persist,
                         cudaFuncAttributeMaxDynamicSharedMemorySize, SCAN_SMEM);
    cudaFuncSetAttribute(k_gemm_mma,
                         cudaFuncAttributeMaxDynamicSharedMemorySize, GEMM_SMEM);

    // 0) zero states + barrier counters
    k_zero<<<2048, 256>>>();

    // 1) split x (permuted) and B weights to bf16 hi/lo
    k_split_x<<<GM, 128>>>(x);
    k_split_w<<<HS, 128>>>(Bw);

    // 2) bx = x @ B^T via mma.sync bf16x3 -> g_bxc
    k_gemm_mma<<<dim3(4, 256), 256, GEMM_SMEM>>>(nullptr, 1);

    // 3) A^32 by fused repeated squaring
    k_sq_fused<<<64, 128>>>(Aw);

    // 4) phase 1: local scans (zero init), persistent   [ncu -s 5 profiles this]
    k_scan_persist<<<dim3(8, 16), 256, SCAN_SMEM>>>(0, nullptr, 0, Aw);

    // 5) phase 2: cross-chunk scan, persistent
    k_cross_persist<<<32, 256>>>();

    // 6) phase 3: local scans, writes hs + bf16 splits for ys GEMM
    k_scan_persist<<<dim3(8, 16), 256, SCAN_SMEM>>>(1, hsp, hsmode, Aw);

    // 7) split C weights, then ys = hs @ C^T via mma.sync bf16x3
    k_split_w<<<HS, 128>>>(Cw);
    k_gemm_mma<<<dim3(4, 256), 256, GEMM_SMEM>>>(out, 0);
}

// round 9
// speedup vs baseline: 2.4391x; 1.2418x over previous
#include <cuda_runtime.h>
#include <cuda_bf16.h>
#include <cstdint>
#include <cstddef>

#define HS 512
#define BS 16
#define SS 2048
#define LC 32              // chunk length
#define CC 64              // number of chunks
#define MR (CC*BS)         // 1024 rows per scan step
#define GM 32768           // big-GEMM M (BS*SS)

// ---------------- scratch (static __device__; no allocation anywhere) ----------------
static __device__ float g_bxc[(size_t)SS * BS * HS];   // [i][chunk][b][h]
static __device__ float g_hs [(size_t)BS * SS * HS];   // fallback hs storage
static __device__ float g_H0[MR * HS];
static __device__ float g_H1[MR * HS];
static __device__ float g_Hi[MR * HS];                 // chunk initial states
static __device__ float g_P0[HS * HS];
static __device__ float g_P1[HS * HS];
static __device__ __nv_bfloat16 g_Ahi[(size_t)GM * HS];  // big-GEMM A operand hi
static __device__ __nv_bfloat16 g_Alo[(size_t)GM * HS];  // big-GEMM A operand lo
static __device__ __nv_bfloat16 g_Whi[HS * HS];
static __device__ __nv_bfloat16 g_Wlo[HS * HS];
static __device__ __nv_bfloat16 g_Hbh0[MR * HS];       // scan H bf16 hi, buf 0
static __device__ __nv_bfloat16 g_Hbl0[MR * HS];       // scan H bf16 lo, buf 0
static __device__ __nv_bfloat16 g_Hbh1[MR * HS];       // buf 1
static __device__ __nv_bfloat16 g_Hbl1[MR * HS];
static __device__ unsigned g_cntA[16];                 // per-row-tile scan barrier
static __device__ unsigned g_cnt3;                     // cross-scan barrier
static __device__ unsigned g_cntS;                     // fused-squaring barrier

// ---------------- warp MMA helpers (sm_80-era, valid on sm_100 base) ----------------
__device__ __forceinline__ uint32_t smem_u32(const void* p) {
    uint32_t a;
    asm("{ .reg .u64 t; cvta.to.shared.u64 t, %1; cvt.u32.u64 %0, t; }" : "=r"(a) : "l"(p));
    return a;
}
__device__ __forceinline__ void ldmx4(uint32_t* r, uint32_t addr)
{
    asm volatile("ldmatrix.sync.aligned.m8n8.x4.shared.b16 {%0,%1,%2,%3}, [%4];"
        : "=r"(r[0]), "=r"(r[1]), "=r"(r[2]), "=r"(r[3]) : "r"(addr));
}
__device__ __forceinline__ void mma16816(float* c, const uint32_t* a, const uint32_t* b)
{
    asm volatile(
        "mma.sync.aligned.m16n8k16.row.col.f32.bf16.bf16.f32 "
        "{%0,%1,%2,%3}, {%4,%5,%6,%7}, {%8,%9}, {%0,%1,%2,%3};"
        : "+f"(c[0]), "+f"(c[1]), "+f"(c[2]), "+f"(c[3])
        : "r"(a[0]), "r"(a[1]), "r"(a[2]), "r"(a[3]), "r"(b[0]), "r"(b[1]));
}

// ---------------- fp32 -> bf16 hi/lo splits ----------------
__device__ __forceinline__ void split4(float4 v, uint2& h, uint2& l)
{
    __nv_bfloat162 h01 = __floats2bfloat162_rn(v.x, v.y);
    __nv_bfloat162 h23 = __floats2bfloat162_rn(v.z, v.w);
    float2 f01 = __bfloat1622float2(h01);
    float2 f23 = __bfloat1622float2(h23);
    __nv_bfloat162 l01 = __floats2bfloat162_rn(v.x - f01.x, v.y - f01.y);
    __nv_bfloat162 l23 = __floats2bfloat162_rn(v.z - f23.x, v.w - f23.y);
    h.x = *reinterpret_cast<uint32_t*>(&h01);
    h.y = *reinterpret_cast<uint32_t*>(&h23);
    l.x = *reinterpret_cast<uint32_t*>(&l01);
    l.y = *reinterpret_cast<uint32_t*>(&l23);
}
__device__ __forceinline__ void split2(float a, float b, uint32_t& h, uint32_t& l)
{
    __nv_bfloat162 hh = __floats2bfloat162_rn(a, b);
    float2 f = __bfloat1622float2(hh);
    __nv_bfloat162 ll = __floats2bfloat162_rn(a - f.x, b - f.y);
    h = *reinterpret_cast<uint32_t*>(&hh);
    l = *reinterpret_cast<uint32_t*>(&ll);
}

// ---------------- global barrier (co-resident grids only) ----------------
__device__ __forceinline__ void gbar(unsigned* cnt, unsigned target)
{
    __threadfence();
    __syncthreads();
    if (threadIdx.x == 0) {
        atomicAdd(cnt, 1u);
        while (*(volatile unsigned*)cnt < target) { __nanosleep(40); }
        __threadfence();
    }
    __syncthreads();
}

// ---------------- zero init ----------------
__global__ void k_zero()
{
    int i = blockIdx.x * blockDim.x + threadIdx.x;
    if (i < MR * HS) { g_H0[i] = 0.f; g_Hi[i] = 0.f; }
    if (i < MR * HS / 2) {               // bf16 buf0 as uint32
        ((unsigned*)g_Hbh0)[i] = 0u;
        ((unsigned*)g_Hbl0)[i] = 0u;
    }
    if (i < 16) g_cntA[i] = 0u;
    if (i == 16) g_cnt3 = 0u;
    if (i == 17) g_cntS = 0u;
}

// ---------------- split kernels ----------------
__global__ __launch_bounds__(128) void k_split_x(const float* __restrict__ x)
{
    int r  = blockIdx.x;                   // gemm row
    int ii = r >> 10;
    int jb = r & 1023;
    int srow = (jb & 15) * SS + ((jb >> 4) << 5) + ii;
    int c = threadIdx.x << 2;
    float4 v = *(const float4*)&x[(size_t)srow * HS + c];
    uint2 h, l;
    split4(v, h, l);
    *(uint2*)&g_Ahi[(size_t)r * HS + c] = h;
    *(uint2*)&g_Alo[(size_t)r * HS + c] = l;
}

__global__ __launch_bounds__(128) void k_split_w(const float* __restrict__ W)
{
    int r = blockIdx.x;
    int c = threadIdx.x << 2;
    float4 v = *(const float4*)&W[(size_t)r * HS + c];
    uint2 h, l;
    split4(v, h, l);
    *(uint2*)&g_Whi[(size_t)r * HS + c] = h;
    *(uint2*)&g_Wlo[(size_t)r * HS + c] = l;
}

// split g_Hi (cross-scan output) into scan bf16 buf 0
__global__ __launch_bounds__(128) void k_split_hi()
{
    int r = blockIdx.x;
    int c = threadIdx.x << 2;
    float4 v = *(const float4*)&g_Hi[(size_t)r * HS + c];
    uint2 h, l;
    split4(v, h, l);
    *(uint2*)&g_Hbh0[(size_t)r * HS + c] = h;
    *(uint2*)&g_Hbl0[(size_t)r * HS + c] = l;
}

// ---------------- bf16x3 big GEMM via mma.sync (proven round 6) ----------------
#define GEMM_SMEM (4 * 128 * 72 * 2)     // 73728 bytes

__global__ __launch_bounds__(256) void k_gemm_mma(float* __restrict__ Out, int mode)
{
    if (mode == 1) Out = g_bxc;
    extern __shared__ __nv_bfloat16 sb[];
    __nv_bfloat16* sAh = sb;
    __nv_bfloat16* sAl = sb + 9216;
    __nv_bfloat16* sWh = sb + 18432;
    __nv_bfloat16* sWl = sb + 27648;

    const int tid  = threadIdx.x;
    const int lane = tid & 31;
    const int wid  = tid >> 5;
    const int row0 = blockIdx.y << 7;
    const int col0 = blockIdx.x << 7;
    const int wm   = wid >> 2;
    const int wn   = wid & 3;

    const int lrow = tid >> 1;
    const int lseg = (tid & 1) << 5;

    float acc[4][4][4];
#pragma unroll
    for (int mt = 0; mt < 4; ++mt)
#pragma unroll
        for (int nt = 0; nt < 4; ++nt)
#pragma unroll
            for (int q = 0; q < 4; ++q) acc[mt][nt][q] = 0.f;

    const uint32_t sAh32 = smem_u32(sAh);
    const uint32_t sAl32 = smem_u32(sAl);
    const uint32_t sWh32 = smem_u32(sWh);
    const uint32_t sWl32 = smem_u32(sWl);

    const uint32_t a_lrow = (uint32_t)(wm * 64 + (lane & 15));
    const uint32_t b_lrow = (uint32_t)(wn * 32 + (lane & 15));
    const uint32_t khalf  = (uint32_t)((lane >> 4) << 3);

    for (int kc = 0; kc < 8; ++kc) {
        __syncthreads();
        {
            const size_t gA = (size_t)(row0 + lrow) * HS + kc * 64 + lseg;
            const size_t gW = (size_t)(col0 + lrow) * HS + kc * 64 + lseg;
            const uint32_t so = (uint32_t)(lrow * 72 + lseg);
#pragma unroll
            for (int i = 0; i < 4; ++i) {
                *(uint4*)(sAh + so + i*8) = *(const uint4*)(g_Ahi + gA + i*8);
                *(uint4*)(sAl + so + i*8) = *(const uint4*)(g_Alo + gA + i*8);
                *(uint4*)(sWh + so + i*8) = *(const uint4*)(g_Whi + gW + i*8);
                *(uint4*)(sWl + so + i*8) = *(const uint4*)(g_Wlo + gW + i*8);
            }
        }
        __syncthreads();

#pragma unroll
        for (int ks = 0; ks < 4; ++ks) {
            const uint32_t kcol = (uint32_t)(ks * 16) + khalf;
            uint32_t ah[4][4], al[4][4], bh[4][2], bl[4][2];
#pragma unroll
            for (int mt = 0; mt < 4; ++mt) {
                uint32_t off = ((a_lrow + mt*16) * 72 + kcol) * 2;
                ldmx4(ah[mt], sAh32 + off);
                ldmx4(al[mt], sAl32 + off);
            }
#pragma unroll
            for (int bt = 0; bt < 2; ++bt) {
                uint32_t off = ((b_lrow + bt*16) * 72 + kcol) * 2;
                uint32_t qh[4], ql[4];
                ldmx4(qh, sWh32 + off);
                ldmx4(ql, sWl32 + off);
                bh[2*bt+0][0] = qh[0]; bh[2*bt+0][1] = qh[2];
                bh[2*bt+1][0] = qh[1]; bh[2*bt+1][1] = qh[3];
                bl[2*bt+0][0] = ql[0]; bl[2*bt+0][1] = ql[2];
                bl[2*bt+1][0] = ql[1]; bl[2*bt+1][1] = ql[3];
            }
#pragma unroll
            for (int mt = 0; mt < 4; ++mt)
#pragma unroll
                for (int nt = 0; nt < 4; ++nt) {
                    mma16816(acc[mt][nt], ah[mt], bh[nt]);
                    mma16816(acc[mt][nt], ah[mt], bl[nt]);
                    mma16816(acc[mt][nt], al[mt], bh[nt]);
                }
        }
    }

    const int r_base = row0 + wm * 64 + (lane >> 2);
    const int c_base = col0 + wn * 32 + ((lane & 3) << 1);
#pragma unroll
    for (int mt = 0; mt < 4; ++mt)
#pragma unroll
        for (int nt = 0; nt < 4; ++nt) {
            size_t o0 = (size_t)(r_base + mt*16)     * HS + c_base + nt*8;
            size_t o1 = (size_t)(r_base + mt*16 + 8) * HS + c_base + nt*8;
            *(float2*)&Out[o0] = make_float2(acc[mt][nt][0], acc[mt][nt][1]);
            *(float2*)&Out[o1] = make_float2(acc[mt][nt][2], acc[mt][nt][3]);
        }
}

// ---------------- persistent tensor-core scan ----------------
// H_out[r][n] = sum_k H_in[r][k]*A[n][k] + bx[r][n], bf16x3 on mma.sync.
// Grid (8 col-tiles x 16 row-tiles), 256 thr, CTA tile 64x64.
// A-weights bf16 hi/lo resident in smem: [8 kc][64 rows][72] each.
#define SCANT_SMEM ((8*64*72*2 + 64*72*2) * 2)   // 165888 bytes

__global__ __launch_bounds__(256) void k_scan_mma(int phase, float* __restrict__ hsp,
                                                  int hsmode, const float* __restrict__ Aw)
{
    extern __shared__ __nv_bfloat16 sx[];
    __nv_bfloat16* sAh = sx;                       // [8][64][72]
    __nv_bfloat16* sAl = sx + 36864;
    __nv_bfloat16* sHh = sx + 73728;               // [64][72]
    __nv_bfloat16* sHl = sx + 73728 + 4608;

    const int tid  = threadIdx.x;
    const int lane = tid & 31;
    const int wid  = tid >> 5;
    const int wm   = wid >> 2;          // 0..1
    const int wn   = wid & 3;           // 0..3
    const int col0 = blockIdx.x << 6;
    const int rb   = blockIdx.y;
    const int row0 = rb << 6;

    if (hsmode == 2) hsp = g_hs;

    // one-time: split A rows [col0, col0+64) into resident bf16 hi/lo
    for (int e = tid; e < 64 * 128; e += 256) {
        int row = e >> 7;
        int c4  = (e & 127) << 2;
        float4 v = *(const float4*)&Aw[(size_t)(col0 + row) * HS + c4];
        uint2 h, l;
        split4(v, h, l);
        int off = ((c4 >> 6) * 4608) + row * 72 + (c4 & 63);
        *(uint2*)&sAh[off] = h;
        *(uint2*)&sAl[off] = l;
    }
    __syncthreads();

    const uint32_t sAh32 = smem_u32(sAh), sAl32 = smem_u32(sAl);
    const uint32_t sHh32 = smem_u32(sHh), sHl32 = smem_u32(sHl);

    const uint32_t a_lrow = (uint32_t)(wm * 32 + (lane & 15));
    const uint32_t b_lrow = (uint32_t)(wn * 16 + (lane & 15));
    const uint32_t khalf  = (uint32_t)((lane >> 4) << 3);
    const int srow = tid >> 2;           // stage row 0..63
    const int sseg = (tid & 3) << 4;     // stage seg 0/16/32/48 halves

    const unsigned base = phase ? (8u * LC) : 0u;
    unsigned* cnt = &g_cntA[rb];

    for (int i = 0; i < LC; ++i) {
        const __nv_bfloat16* Hh = (i & 1) ? g_Hbh1 : g_Hbh0;
        const __nv_bfloat16* Hl = (i & 1) ? g_Hbl1 : g_Hbl0;
        __nv_bfloat16* Oh = (i & 1) ? g_Hbh0 : g_Hbh1;
        __nv_bfloat16* Ol = (i & 1) ? g_Hbl0 : g_Hbl1;
        float* Hout = (i & 1) ? g_H0 : g_H1;     // fp32 states (finals for cross)
        const float* bxs = g_bxc + (size_t)i * MR * HS;

        float acc[2][2][4];
#pragma unroll
        for (int mt = 0; mt < 2; ++mt)
#pragma unroll
            for (int nt = 0; nt < 2; ++nt)
#pragma unroll
                for (int q = 0; q < 4; ++q) acc[mt][nt][q] = 0.f;

        for (int kc = 0; kc < 8; ++kc) {
            __syncthreads();
            {
                size_t g = (size_t)(row0 + srow) * HS + kc * 64 + sseg;
                int so = srow * 72 + sseg;
                *(uint4*)&sHh[so]     = *(const uint4*)&Hh[g];
                *(uint4*)&sHh[so + 8] = *(const uint4*)&Hh[g + 8];
                *(uint4*)&sHl[so]     = *(const uint4*)&Hl[g];
                *(uint4*)&sHl[so + 8] = *(const uint4*)&Hl[g + 8];
            }
            __syncthreads();
            const uint32_t bbase = (uint32_t)(kc * 4608);
#pragma unroll
            for (int ks = 0; ks < 4; ++ks) {
                const uint32_t kcol = (uint32_t)(ks * 16) + khalf;
                uint32_t ah[2][4], al[2][4];
#pragma unroll
                for (int mt = 0; mt < 2; ++mt) {
                    uint32_t off = ((a_lrow + mt*16) * 72 + kcol) * 2;
                    ldmx4(ah[mt], sHh32 + off);
                    ldmx4(al[mt], sHl32 + off);
                }
                uint32_t qh[4], ql[4];
                {
                    uint32_t off = (bbase + b_lrow * 72 + kcol) * 2;
                    ldmx4(qh, sAh32 + off);
                    ldmx4(ql, sAl32 + off);
                }
                uint32_t bh[2][2] = {{qh[0], qh[2]}, {qh[1], qh[3]}};
                uint32_t bl[2][2] = {{ql[0], ql[2]}, {ql[1], ql[3]}};
#pragma unroll
                for (int mt = 0; mt < 2; ++mt)
#pragma unroll
                    for (int nt = 0; nt < 2; ++nt) {
                        mma16816(acc[mt][nt], ah[mt], bh[nt]);
                        mma16816(acc[mt][nt], ah[mt], bl[nt]);
                        mma16816(acc[mt][nt], al[mt], bh[nt]);
                    }
            }
        }

        // epilogue: add bx, write fp32 state + bf16 pair (+ hs outputs in phase 3)
        const int r_b = row0 + wm * 32 + (lane >> 2);
        const int c_b = col0 + wn * 16 + ((lane & 3) << 1);
#pragma unroll
        for (int mt = 0; mt < 2; ++mt)
#pragma unroll
            for (int nt = 0; nt < 2; ++nt) {
                int r0 = r_b + mt * 16;
                int c  = c_b + nt * 8;
                size_t o0 = (size_t)r0 * HS + c;
                size_t o1 = (size_t)(r0 + 8) * HS + c;
                float2 b0 = *(const float2*)&bxs[o0];
                float2 b1 = *(const float2*)&bxs[o1];
                float v00 = acc[mt][nt][0] + b0.x, v01 = acc[mt][nt][1] + b0.y;
                float v10 = acc[mt][nt][2] + b1.x, v11 = acc[mt][nt][3] + b1.y;
                *(float2*)&Hout[o0] = make_float2(v00, v01);
                *(float2*)&Hout[o1] = make_float2(v10, v11);
                uint32_t h0, l0, h1, l1;
                split2(v00, v01, h0, l0);
                split2(v10, v11, h1, l1);
                *(uint32_t*)&Oh[o0] = h0;  *(uint32_t*)&Ol[o0] = l0;
                *(uint32_t*)&Oh[o1] = h1;  *(uint32_t*)&Ol[o1] = l1;
                if (hsmode) {
                    size_t ho0 = ((size_t)(r0 & 15) * SS + ((r0 >> 4) << 5) + i) * HS + c;
                    int r1 = r0 + 8;
                    size_t ho1 = ((size_t)(r1 & 15) * SS + ((r1 >> 4) << 5) + i) * HS + c;
                    *(float2*)&hsp[ho0] = make_float2(v00, v01);
                    *(float2*)&hsp[ho1] = make_float2(v10, v11);
                    *(uint32_t*)&g_Ahi[ho0] = h0;  *(uint32_t*)&g_Alo[ho0] = l0;
                    *(uint32_t*)&g_Ahi[ho1] = h1;  *(uint32_t*)&g_Alo[ho1] = l1;
                }
            }
        gbar(cnt, base + 8u * (i + 1));
    }
}

// ---------------- fused squarings: A^32 via 5 squarings, one launch ----------------
__global__ __launch_bounds__(128) void k_sq_fused(const float* __restrict__ A0)
{
    __shared__ float sI[16][68];
    __shared__ float sW[16][68];

    const int tid  = threadIdx.x;
    const int row0 = (blockIdx.x >> 3) << 6;
    const int col0 = (blockIdx.x & 7) << 6;
    const int lr   = tid >> 1;
    const int lk   = (tid & 1) << 3;
    const int kk2  = tid >> 4;
    const int nq   = (tid & 15) << 2;
    const int tx = tid & 7, ty = tid >> 3;

    for (int s = 0; s < 5; ++s) {
        const float* X;
        float* Outp;
        if (s == 0)      { X = A0;   Outp = g_P0; }
        else if (s & 1)  { X = g_P0; Outp = g_P1; }
        else             { X = g_P1; Outp = g_P0; }

        const float* ip = X + (size_t)(row0 + lr) * HS + lk;

        float acc[4][8];
#pragma unroll
        for (int i = 0; i < 4; i++)
#pragma unroll
            for (int j = 0; j < 8; j++) acc[i][j] = 0.f;

        for (int k0 = 0; k0 < HS; k0 += 16) {
            float4 a0 = *(const float4*)(ip + k0);
            float4 a1 = *(const float4*)(ip + k0 + 4);
            float4 y0 = *(const float4*)&X[(size_t)(k0 + kk2)     * HS + col0 + nq];
            float4 y1 = *(const float4*)&X[(size_t)(k0 + kk2 + 8) * HS + col0 + nq];
            sI[lk+0][lr]=a0.x; sI[lk+1][lr]=a0.y; sI[lk+2][lr]=a0.z; sI[lk+3][lr]=a0.w;
            sI[lk+4][lr]=a1.x; sI[lk+5][lr]=a1.y; sI[lk+6][lr]=a1.z; sI[lk+7][lr]=a1.w;
            *(float4*)&sW[kk2][nq]     = y0;
            *(float4*)&sW[kk2 + 8][nq] = y1;
            __syncthreads();
#pragma unroll
            for (int k = 0; k < 16; k++) {
                float4 ri = *(const float4*)&sI[k][ty << 2];
                float4 w0 = *(const float4*)&sW[k][tx << 3];
                float4 w1 = *(const float4*)&sW[k][(tx << 3) + 4];
                float rr[4] = {ri.x, ri.y, ri.z, ri.w};
                float ww[8] = {w0.x, w0.y, w0.z, w0.w, w1.x, w1.y, w1.z, w1.w};
#pragma unroll
                for (int i = 0; i < 4; i++)
#pragma unroll
                    for (int j = 0; j < 8; j++) acc[i][j] += rr[i] * ww[j];
            }
            __syncthreads();
        }
#pragma unroll
        for (int i = 0; i < 4; i++) {
            size_t o = (size_t)(row0 + (ty << 2) + i) * HS + col0 + (tx << 3);
            *(float4*)&Outp[o]     = make_float4(acc[i][0], acc[i][1], acc[i][2], acc[i][3]);
            *(float4*)&Outp[o + 4] = make_float4(acc[i][4], acc[i][5], acc[i][6], acc[i][7]);
        }
        gbar(&g_cntS, 64u * (unsigned)(s + 1));
    }
}

// ---------------- persistent cross-chunk scan ----------------
__global__ __launch_bounds__(256) void k_cross_persist()
{
    __shared__ float sS[16][516];
    const float* AL = g_P0;              // A^32
    const int t  = threadIdx.x;
    const int n0 = blockIdx.x << 4;
    const int r  = t & 15;
    const int no = t >> 4;
    const int n  = n0 + no;
    const float* arow = AL + (size_t)n * HS;

    for (int j = 1; j < CC; ++j) {
        const float* sprev = g_Hi + (size_t)(j - 1) * BS * HS;
        const float* fprev = g_H0 + (size_t)(j - 1) * BS * HS;
        float*       sout  = g_Hi + (size_t)j * BS * HS;

        for (int e = t; e < BS * HS / 4; e += 256) {
            float4 v = ((const float4*)sprev)[e];
            int rr = e >> 7;
            int kk = (e & 127) << 2;
            *(float4*)&sS[rr][kk] = v;
        }
        __syncthreads();

        float a0 = 0.f, a1 = 0.f, a2 = 0.f, a3 = 0.f;
#pragma unroll 4
        for (int k = 0; k < HS; k += 16) {
            float4 v0 = *(const float4*)&arow[k];
            float4 v1 = *(const float4*)&arow[k + 4];
            float4 v2 = *(const float4*)&arow[k + 8];
            float4 v3 = *(const float4*)&arow[k + 12];
            a0 += v0.x*sS[r][k+0]  + v0.y*sS[r][k+1]  + v0.z*sS[r][k+2]  + v0.w*sS[r][k+3];
            a1 += v1.x*sS[r][k+4]  + v1.y*sS[r][k+5]  + v1.z*sS[r][k+6]  + v1.w*sS[r][k+7];
            a2 += v2.x*sS[r][k+8]  + v2.y*sS[r][k+9]  + v2.z*sS[r][k+10] + v2.w*sS[r][k+11];
            a3 += v3.x*sS[r][k+12] + v3.y*sS[r][k+13] + v3.z*sS[r][k+14] + v3.w*sS[r][k+15];
        }
        sout[(size_t)r * HS + n] = (a0 + a1) + (a2 + a3) + fprev[(size_t)r * HS + n];
        gbar(&g_cnt3, 32u * (unsigned)j);
    }
}

// ---------------- launch ----------------
extern "C" void kernel_launch(void* const* d_in, const int* in_sizes, int n_in,
                              void* d_out, int out_size)
{
    const float* x  = (const float*)d_in[0];
    const float* Aw = (const float*)d_in[1];
    const float* Bw = (const float*)d_in[2];
    const float* Cw = (const float*)d_in[3];
    float* out = (float*)d_out;

    const size_t YS = (size_t)BS * SS * HS;
    bool both = (size_t)out_size >= 2 * YS;     // output = (ys, hs) concatenated
    float* hsp = both ? out + YS : nullptr;
    int hsmode = both ? 1 : 2;

    cudaFuncSetAttribute(k_scan_mma,
                         cudaFuncAttributeMaxDynamicSharedMemorySize, SCANT_SMEM);
    cudaFuncSetAttribute(k_gemm_mma,
                         cudaFuncAttributeMaxDynamicSharedMemorySize, GEMM_SMEM);

    // 0) zero states + bf16 buf0 + barrier counters
    k_zero<<<2048, 256>>>();

    // 1) split x (permuted) and B weights to bf16 hi/lo
    k_split_x<<<GM, 128>>>(x);
    k_split_w<<<HS, 128>>>(Bw);

    // 2) bx = x @ B^T via mma.sync bf16x3 -> g_bxc
    k_gemm_mma<<<dim3(4, 256), 256, GEMM_SMEM>>>(nullptr, 1);

    // 3) A^32 by fused repeated squaring
    k_sq_fused<<<64, 128>>>(Aw);

    // 4) phase 1: tensor-core local scans (zero init)   [ncu -s 5 profiles this]
    k_scan_mma<<<dim3(8, 16), 256, SCANT_SMEM>>>(0, nullptr, 0, Aw);

    // 5) phase 2: cross-chunk scan, persistent
    k_cross_persist<<<32, 256>>>();

    // 6) seed phase-3 initial states (bf16 split of g_Hi)
    k_split_hi<<<MR, 128>>>();

    // 7) phase 3: tensor-core local scans, writes hs + ys-GEMM operands
    k_scan_mma<<<dim3(8, 16), 256, SCANT_SMEM>>>(1, hsp, hsmode, Aw);

    // 8) split C weights, then ys = hs @ C^T via mma.sync bf16x3
    k_split_w<<<HS, 128>>>(Cw);
    k_gemm_mma<<<dim3(4, 256), 256, GEMM_SMEM>>>(out, 0);
}